// round 7
// baseline (speedup 1.0000x reference)
#include <cuda_runtime.h>

// B=16, C=2048, H=2, HS=64, HOD=1, D_MODEL=2  -- single fused kernel.
// Collapsed: M_h = Wq_h Wk_h^T (2x2), g_h = Wv_h Wo_h (2,)
//   t(c,f) = xp_c^T M_h xp_f / 8;  o_h(c) = sum_{f<=c} e^t (g_h.xp_f) / sum e^t
// Taylor: e^{p.y} = sum_{j+i<=12} (p0^j/j!)(p1^i/i!) y0^j y1^i
// => causal sums = polynomial in prefix moments M_{j,i} = sum_f y0^j y1^i (j+i<=13).
// Block (b,r) owns queries [256r,256r+256) = chunks 4r..4r+3 (chunk = 64 f).
// It computes its own 4 chunks' moments (warps 0-27), publishes them to global
// with a fence+counter handshake, while warps 28-31 spin-load the prefix base
// from earlier blocks. Tails (exact exp over own chunk) overlap on spare warps.

#define CC    2048
#define NMOM  105           // #{(j,i): j+i<=13}
#define LOG2E 1.4426950408889634f

__device__ float g_mom[16][32][NMOM];   // per (batch, chunk) raw moments
__device__ int   g_cnt[16][8];          // producer counters (monotone; never reset)

__device__ __forceinline__ int midx(int j, int i) {
    return j * 14 - (j * (j - 1)) / 2 + i;
}

__device__ __forceinline__ float ex2f(float v) {
    float y;
    asm("ex2.approx.ftz.f32 %0, %1;" : "=f"(y) : "f"(v));
    return y;
}

__global__ __launch_bounds__(1024, 1)
void mha_fused(const float* __restrict__ x,
               const float* __restrict__ Wq,
               const float* __restrict__ Wk,
               const float* __restrict__ Wv,
               const float* __restrict__ Wo,
               const float* __restrict__ Wb,
               float* __restrict__ out)
{
    __shared__ float2 sY[256];         // xp window
    __shared__ float  sM[2][2][2];     // M[h][i][j]
    __shared__ float  sG[2][2];        // g[h][i]
    __shared__ float  sBase[NMOM];     // prefix over chunks < 4r
    __shared__ float  sOwn[4][NMOM];   // own 4 chunks' moments
    __shared__ float  sPre[4][NMOM];   // per-quad prefixes
    __shared__ float4 sT[2][256];      // tail partials {den, a0, a1} per (h, c)
    __shared__ float2 sO[256];         // per-head outputs

    const int tid  = threadIdx.x;
    const int b    = blockIdx.x >> 3;
    const int r    = blockIdx.x & 7;
    const int wid  = tid >> 5, lane = tid & 31;

    // ================= phase 0: concurrent setup =================
    if (tid < 256) {
        const int f = r * 256 + tid;
        const float2 v = reinterpret_cast<const float2*>(x)[b * CC + f];
        sY[tid] = make_float2(v.x + sinf((float)f), v.y + cosf((float)f));
    } else if (tid < 448) {
        // 12 length-64 dot products for M and g (16 lanes each)
        const int grp = (tid - 256) >> 4, l16 = tid & 15;
        const float *pa, *pb;
        if (grp < 8) {
            const int h = grp >> 2, i = (grp >> 1) & 1, jj = grp & 1;
            pa = Wq + h * 128 + i * 64;
            pb = Wk + h * 128 + jj * 64;
        } else {
            const int g2 = grp - 8, h = g2 >> 1, i = g2 & 1;
            pa = Wv + h * 128 + i * 64;
            pb = Wo + h * 64;
        }
        float s = 0.f;
        #pragma unroll
        for (int e = 0; e < 4; ++e) s = fmaf(pa[l16 * 4 + e], pb[l16 * 4 + e], s);
        #pragma unroll
        for (int off = 8; off; off >>= 1) s += __shfl_down_sync(0xffffffffu, s, off, 16);
        if (l16 == 0) {
            if (grp < 8) sM[grp >> 2][(grp >> 1) & 1][grp & 1] = s;
            else         sG[(grp - 8) >> 1][(grp - 8) & 1]     = s;
        }
    } else if (tid >= 896) {
        // warps 28-31: spin on earlier blocks' flags, accumulate prefix base
        const int m = tid - 896;
        if (m < NMOM) {
            float s = 0.f;
            for (int g = 0; g < r; ++g) {
                volatile int* fl = &g_cnt[b][g];
                while (*fl < 28) __nanosleep(64);
                __threadfence();                 // acquire: order moment loads after flag
                s += g_mom[b][4 * g + 0][m] + g_mom[b][4 * g + 1][m]
                   + g_mom[b][4 * g + 2][m] + g_mom[b][4 * g + 3][m];
            }
            sBase[m] = s;
        }
    }
    __syncthreads();   // sync1: sY, sM/sG, sBase ready

    // ================= phase A: moments (warps 0-27) | tails 0-127 (warps 28-31)
    if (wid < 28) {
        const int j  = wid >> 1;        // moment row 0..13
        const int hf = wid & 1;         // 128-half of window
        float acc0[14], acc1[14];
        #pragma unroll
        for (int i = 0; i < 14; ++i) { acc0[i] = 0.f; acc1[i] = 0.f; }

        #pragma unroll
        for (int ff = 0; ff < 2; ++ff) {        // chunk cs=0 of this half
            const float2 y = sY[hf * 128 + ff * 32 + lane];
            float c0 = 1.f;
            for (int t = 0; t < j; ++t) c0 *= y.x;
            float vv = c0;
            #pragma unroll
            for (int i = 0; i < 14; ++i) { acc0[i] += vv; vv *= y.y; }
        }
        #pragma unroll
        for (int ff = 2; ff < 4; ++ff) {        // chunk cs=1
            const float2 y = sY[hf * 128 + ff * 32 + lane];
            float c0 = 1.f;
            for (int t = 0; t < j; ++t) c0 *= y.x;
            float vv = c0;
            #pragma unroll
            for (int i = 0; i < 14; ++i) { acc1[i] += vv; vv *= y.y; }
        }
        #pragma unroll
        for (int i = 0; i < 14; ++i) {
            float s0 = acc0[i], s1 = acc1[i];
            #pragma unroll
            for (int off = 16; off; off >>= 1) {
                s0 += __shfl_down_sync(0xffffffffu, s0, off);
                s1 += __shfl_down_sync(0xffffffffu, s1, off);
            }
            acc0[i] = s0; acc1[i] = s1;
        }
        if (lane == 0) {
            const int cb = 2 * hf;
            for (int i = 0; i + j <= 13; ++i) {
                const int m = midx(j, i);
                sOwn[cb + 0][m] = acc0[i];
                sOwn[cb + 1][m] = acc1[i];
                g_mom[b][4 * r + cb + 0][m] = acc0[i];
                g_mom[b][4 * r + cb + 1][m] = acc1[i];
            }
            __threadfence();
            atomicAdd(&g_cnt[b][r], 1);
        }
    } else {
        // tails tasks 0..127: h=0, c_loc = tid-896
        const int c_loc = tid - 896;
        const float2 yc = sY[c_loc];
        const float p0 = (sM[0][0][0] * yc.x + sM[0][1][0] * yc.y) * (0.125f * LOG2E);
        const float p1 = (sM[0][0][1] * yc.x + sM[0][1][1] * yc.y) * (0.125f * LOG2E);
        float den = 0.f, a0 = 0.f, a1 = 0.f;
        for (int fl = c_loc & ~63; fl <= c_loc; ++fl) {
            const float2 yf = sY[fl];
            const float e = ex2f(fmaf(yf.x, p0, yf.y * p1));
            den += e; a0 = fmaf(e, yf.x, a0); a1 = fmaf(e, yf.y, a1);
        }
        sT[0][c_loc] = make_float4(den, a0, a1, 0.f);
    }
    __syncthreads();   // sync2: sOwn ready

    // ================= phase B: build sPre (tid<105) | tails 128-511 (tid 512-895)
    if (tid < NMOM) {
        const float bse = sBase[tid];
        const float o0 = sOwn[0][tid], o1 = sOwn[1][tid], o2 = sOwn[2][tid];
        sPre[0][tid] = bse;
        sPre[1][tid] = bse + o0;
        sPre[2][tid] = bse + o0 + o1;
        sPre[3][tid] = bse + o0 + o1 + o2;
    } else if (tid >= 512 && tid < 896) {
        const int t = tid - 384;               // 128..511
        const int h = t >> 8, c_loc = t & 255;
        const float2 yc = sY[c_loc];
        const float p0 = (sM[h][0][0] * yc.x + sM[h][1][0] * yc.y) * (0.125f * LOG2E);
        const float p1 = (sM[h][0][1] * yc.x + sM[h][1][1] * yc.y) * (0.125f * LOG2E);
        float den = 0.f, a0 = 0.f, a1 = 0.f;
        for (int fl = c_loc & ~63; fl <= c_loc; ++fl) {
            const float2 yf = sY[fl];
            const float e = ex2f(fmaf(yf.x, p0, yf.y * p1));
            den += e; a0 = fmaf(e, yf.x, a0); a1 = fmaf(e, yf.y, a1);
        }
        sT[h][c_loc] = make_float4(den, a0, a1, 0.f);
    }
    __syncthreads();   // sync3: sPre + all tails ready

    // ================= phase C: poly + combine (tid < 512) =================
    if (tid < 512) {
        const int h = tid >> 8, c_loc = tid & 255;
        const int quad = c_loc >> 6;           // warp-uniform
        const float2 yc = sY[c_loc];
        const float p0 = (sM[h][0][0] * yc.x + sM[h][1][0] * yc.y) * 0.125f;
        const float p1 = (sM[h][0][1] * yc.x + sM[h][1][1] * yc.y) * 0.125f;

        const float INV[14] = {0.f, 1.f, 0.5f, 1.f/3.f, 0.25f, 0.2f, 1.f/6.f,
                               1.f/7.f, 0.125f, 1.f/9.f, 0.1f, 1.f/11.f,
                               1.f/12.f, 1.f/13.f};
        float aq[14], bq[14];
        aq[0] = 1.f; bq[0] = 1.f;
        #pragma unroll
        for (int t = 1; t < 14; ++t) {
            aq[t] = aq[t - 1] * p0 * INV[t];
            bq[t] = bq[t - 1] * p1 * INV[t];
        }
        const float* PRE = sPre[quad];
        float sd = 0.f, s0 = 0.f, s1 = 0.f;
        #pragma unroll
        for (int J = 0; J <= 13; ++J) {
            #pragma unroll
            for (int I = 0; I + J <= 13; ++I) {
                const float P = PRE[midx(J, I)];
                const float u = bq[I] * P;
                const float v = aq[J] * P;
                if (J + I <= 12) sd = fmaf(v, bq[I], sd);
                if (J >= 1)      s0 = fmaf(aq[J - 1], u, s0);
                if (I >= 1)      s1 = fmaf(v, bq[I - 1], s1);
            }
        }
        const float4 tt = sT[h][c_loc];
        const float den = sd + tt.x;
        const float A0  = s0 + tt.y;
        const float A1  = s1 + tt.z;
        const float o   = (sG[h][0] * A0 + sG[h][1] * A1) / den;
        if (h == 0) sO[c_loc].x = o; else sO[c_loc].y = o;
    }
    __syncthreads();   // sync4

    if (tid < 256) {
        const float2 o = sO[tid];
        const float b00 = __ldg(Wb + 0), b01 = __ldg(Wb + 1);
        const float b10 = __ldg(Wb + 2), b11 = __ldg(Wb + 3);
        float2 res;
        res.x = fmaf(o.x, b00, o.y * b10);
        res.y = fmaf(o.x, b01, o.y * b11);
        reinterpret_cast<float2*>(out)[b * CC + r * 256 + tid] = res;
    }
}

extern "C" void kernel_launch(void* const* d_in, const int* in_sizes, int n_in,
                              void* d_out, int out_size)
{
    const float* x  = (const float*)d_in[0];
    const float* Wq = (const float*)d_in[1];
    const float* Wk = (const float*)d_in[2];
    const float* Wv = (const float*)d_in[3];
    const float* Wo = (const float*)d_in[4];
    const float* Wb = (const float*)d_in[5];
    float* out = (float*)d_out;

    mha_fused<<<128, 1024>>>(x, Wq, Wk, Wv, Wo, Wb, out);
}

// round 8
// speedup vs baseline: 1.2236x; 1.2236x over previous
#include <cuda_runtime.h>

// B=16, C=2048, H=2, HS=64, HOD=1, D_MODEL=2  -- single fused kernel.
// Collapsed: M_h = Wq_h Wk_h^T (2x2), g_h = Wv_h Wo_h (2,)
//   t(c,f) = xp_c^T M_h xp_f / 8;  o_h(c) = sum_{f<=c} e^t (g_h.xp_f) / sum e^t
// Taylor: e^{p.y} = sum_{j+i<=12} (p0^j/j!)(p1^i/i!) y0^j y1^i
// => causal sums = polynomial in prefix moments M_{j,i} = sum_f y0^j y1^i (j+i<=13).
// Block (b,r) owns queries [256r,256r+256) = chunks 4r..4r+3 (chunk = 64 f).
// KEY (fix vs prev round): producer warps 0-27 sync ONLY among themselves
// (named barrier), publish moments ASAP; consumer warps 28-31 spin on earlier
// blocks' flags in parallel. No cross-block serialization of the moment work.

#define CC    2048
#define NMOM  105           // #{(j,i): j+i<=13}
#define LOG2E 1.4426950408889634f

__device__ float g_mom[16][32][NMOM];   // per (batch, chunk) raw moments
__device__ int   g_cnt[16][8];          // producer counters (monotone; never reset)

__device__ __forceinline__ int midx(int j, int i) {
    return j * 14 - (j * (j - 1)) / 2 + i;
}

__device__ __forceinline__ float ex2f(float v) {
    float y;
    asm("ex2.approx.ftz.f32 %0, %1;" : "=f"(y) : "f"(v));
    return y;
}

__global__ __launch_bounds__(1024, 1)
void mha_fused(const float* __restrict__ x,
               const float* __restrict__ Wq,
               const float* __restrict__ Wk,
               const float* __restrict__ Wv,
               const float* __restrict__ Wo,
               const float* __restrict__ Wb,
               float* __restrict__ out)
{
    __shared__ float2 sY[256];         // xp window
    __shared__ float  sM[2][2][2];     // M[h][i][j]
    __shared__ float  sG[2][2];        // g[h][i]
    __shared__ float  sBase[NMOM];     // prefix over chunks < 4r
    __shared__ float  sOwn[4][NMOM];   // own 4 chunks' moments
    __shared__ float  sPre[4][NMOM];   // per-quad prefixes
    __shared__ float4 sT[2][256];      // tail partials {den, a0, a1} per (h, c)
    __shared__ float2 sO[256];         // per-head outputs

    const int tid  = threadIdx.x;
    const int b    = blockIdx.x >> 3;
    const int r    = blockIdx.x & 7;
    const int wid  = tid >> 5, lane = tid & 31;

    // ================= phase 0 =================
    // producer group (warps 0-27): sY + weight dots; consumer group (28-31): spin.
    if (tid < 256) {
        const int f = r * 256 + tid;
        const float2 v = reinterpret_cast<const float2*>(x)[b * CC + f];
        sY[tid] = make_float2(v.x + sinf((float)f), v.y + cosf((float)f));
    } else if (tid < 448) {
        // 12 length-64 dot products for M and g (16 lanes each)
        const int grp = (tid - 256) >> 4, l16 = tid & 15;
        const float *pa, *pb;
        if (grp < 8) {
            const int h = grp >> 2, i = (grp >> 1) & 1, jj = grp & 1;
            pa = Wq + h * 128 + i * 64;
            pb = Wk + h * 128 + jj * 64;
        } else {
            const int g2 = grp - 8, h = g2 >> 1, i = g2 & 1;
            pa = Wv + h * 128 + i * 64;
            pb = Wo + h * 64;
        }
        float s = 0.f;
        #pragma unroll
        for (int e = 0; e < 4; ++e) s = fmaf(pa[l16 * 4 + e], pb[l16 * 4 + e], s);
        #pragma unroll
        for (int off = 8; off; off >>= 1) s += __shfl_down_sync(0xffffffffu, s, off, 16);
        if (l16 == 0) {
            if (grp < 8) sM[grp >> 2][(grp >> 1) & 1][grp & 1] = s;
            else         sG[(grp - 8) >> 1][(grp - 8) & 1]     = s;
        }
    }

    if (wid < 28) {
        // ---- producer path: join on sY/sM, compute + publish moments, then tails
        asm volatile("bar.sync 1, 896;" ::: "memory");   // warps 0-27 only

        const int j  = wid >> 1;        // moment row 0..13
        const int hf = wid & 1;         // 128-half of window
        float acc0[14], acc1[14];
        #pragma unroll
        for (int i = 0; i < 14; ++i) { acc0[i] = 0.f; acc1[i] = 0.f; }

        #pragma unroll
        for (int ff = 0; ff < 2; ++ff) {        // chunk cs=0 of this half
            const float2 y = sY[hf * 128 + ff * 32 + lane];
            float c0 = 1.f;
            for (int t = 0; t < j; ++t) c0 *= y.x;
            float vv = c0;
            #pragma unroll
            for (int i = 0; i < 14; ++i) { acc0[i] += vv; vv *= y.y; }
        }
        #pragma unroll
        for (int ff = 2; ff < 4; ++ff) {        // chunk cs=1
            const float2 y = sY[hf * 128 + ff * 32 + lane];
            float c0 = 1.f;
            for (int t = 0; t < j; ++t) c0 *= y.x;
            float vv = c0;
            #pragma unroll
            for (int i = 0; i < 14; ++i) { acc1[i] += vv; vv *= y.y; }
        }
        #pragma unroll
        for (int i = 0; i < 14; ++i) {
            float s0 = acc0[i], s1 = acc1[i];
            #pragma unroll
            for (int off = 16; off; off >>= 1) {
                s0 += __shfl_down_sync(0xffffffffu, s0, off);
                s1 += __shfl_down_sync(0xffffffffu, s1, off);
            }
            acc0[i] = s0; acc1[i] = s1;
        }
        if (lane == 0) {
            const int cb = 2 * hf;
            for (int i = 0; i + j <= 13; ++i) {
                const int m = midx(j, i);
                sOwn[cb + 0][m] = acc0[i];
                sOwn[cb + 1][m] = acc1[i];
                g_mom[b][4 * r + cb + 0][m] = acc0[i];
                g_mom[b][4 * r + cb + 1][m] = acc1[i];
            }
            __threadfence();                     // release moments before flag
            atomicAdd(&g_cnt[b][r], 1);
        }

        // ---- tails: tasks tid 0..511 (h = tid>>8, c_loc = tid&255)
        if (tid < 512) {
            const int h = tid >> 8, c_loc = tid & 255;
            const float2 yc = sY[c_loc];
            const float p0 = (sM[h][0][0] * yc.x + sM[h][1][0] * yc.y) * (0.125f * LOG2E);
            const float p1 = (sM[h][0][1] * yc.x + sM[h][1][1] * yc.y) * (0.125f * LOG2E);
            float den = 0.f, a0 = 0.f, a1 = 0.f;
            for (int fl = c_loc & ~63; fl <= c_loc; ++fl) {
                const float2 yf = sY[fl];
                const float e = ex2f(fmaf(yf.x, p0, yf.y * p1));
                den += e; a0 = fmaf(e, yf.x, a0); a1 = fmaf(e, yf.y, a1);
            }
            sT[h][c_loc] = make_float4(den, a0, a1, 0.f);
        }
    } else {
        // ---- consumer path (warps 28-31): spin on earlier blocks, build sBase
        const int m = tid - 896;
        if (m < NMOM) {
            float s = 0.f;
            for (int g = 0; g < r; ++g) {
                volatile int* fl = &g_cnt[b][g];
                while (*fl < 28) __nanosleep(32);
                __threadfence();                 // acquire: order moment loads after flag
                s += g_mom[b][4 * g + 0][m] + g_mom[b][4 * g + 1][m]
                   + g_mom[b][4 * g + 2][m] + g_mom[b][4 * g + 3][m];
            }
            sBase[m] = s;
        }
    }
    __syncthreads();   // join: sOwn, sBase, sT all ready

    // ================= prefix build =================
    if (tid < NMOM) {
        const float bse = sBase[tid];
        const float o0 = sOwn[0][tid], o1 = sOwn[1][tid], o2 = sOwn[2][tid];
        sPre[0][tid] = bse;
        sPre[1][tid] = bse + o0;
        sPre[2][tid] = bse + o0 + o1;
        sPre[3][tid] = bse + o0 + o1 + o2;
    }
    __syncthreads();

    // ================= poly + combine (tid < 512) =================
    if (tid < 512) {
        const int h = tid >> 8, c_loc = tid & 255;
        const int quad = c_loc >> 6;           // warp-uniform
        const float2 yc = sY[c_loc];
        const float p0 = (sM[h][0][0] * yc.x + sM[h][1][0] * yc.y) * 0.125f;
        const float p1 = (sM[h][0][1] * yc.x + sM[h][1][1] * yc.y) * 0.125f;

        const float INV[14] = {0.f, 1.f, 0.5f, 1.f/3.f, 0.25f, 0.2f, 1.f/6.f,
                               1.f/7.f, 0.125f, 1.f/9.f, 0.1f, 1.f/11.f,
                               1.f/12.f, 1.f/13.f};
        float aq[14], bq[14];
        aq[0] = 1.f; bq[0] = 1.f;
        #pragma unroll
        for (int t = 1; t < 14; ++t) {
            aq[t] = aq[t - 1] * p0 * INV[t];
            bq[t] = bq[t - 1] * p1 * INV[t];
        }
        const float* PRE = sPre[quad];
        float sd = 0.f, s0 = 0.f, s1 = 0.f;
        #pragma unroll
        for (int J = 0; J <= 13; ++J) {
            #pragma unroll
            for (int I = 0; I + J <= 13; ++I) {
                const float P = PRE[midx(J, I)];
                const float u = bq[I] * P;
                const float v = aq[J] * P;
                if (J + I <= 12) sd = fmaf(v, bq[I], sd);
                if (J >= 1)      s0 = fmaf(aq[J - 1], u, s0);
                if (I >= 1)      s1 = fmaf(v, bq[I - 1], s1);
            }
        }
        const float4 tt = sT[h][c_loc];
        const float den = sd + tt.x;
        const float A0  = s0 + tt.y;
        const float A1  = s1 + tt.z;
        const float o   = (sG[h][0] * A0 + sG[h][1] * A1) / den;
        if (h == 0) sO[c_loc].x = o; else sO[c_loc].y = o;
    }
    __syncthreads();

    if (tid < 256) {
        const float2 o = sO[tid];
        const float b00 = __ldg(Wb + 0), b01 = __ldg(Wb + 1);
        const float b10 = __ldg(Wb + 2), b11 = __ldg(Wb + 3);
        float2 res;
        res.x = fmaf(o.x, b00, o.y * b10);
        res.y = fmaf(o.x, b01, o.y * b11);
        reinterpret_cast<float2*>(out)[b * CC + r * 256 + tid] = res;
    }
}

extern "C" void kernel_launch(void* const* d_in, const int* in_sizes, int n_in,
                              void* d_out, int out_size)
{
    const float* x  = (const float*)d_in[0];
    const float* Wq = (const float*)d_in[1];
    const float* Wk = (const float*)d_in[2];
    const float* Wv = (const float*)d_in[3];
    const float* Wo = (const float*)d_in[4];
    const float* Wb = (const float*)d_in[5];
    float* out = (float*)d_out;

    mha_fused<<<128, 1024>>>(x, Wq, Wk, Wv, Wo, Wb, out);
}